// round 13
// baseline (speedup 1.0000x reference)
#include <cuda_runtime.h>
#include <cuda_fp16.h>
#include <cstdint>

// B=32, P=512, S=1024, H=1024, R=256, K3=3072
// out[M=16384,256] = feats[M,3072] @ W^T + bias
// R13: R12 (512 thr, 16 warps 4x4, warp tile 32x64, KC=64) +
//  - A-fragment double-buffering across k-steps (fits 128-reg cap: ~116)
//  - NSTAGE=4 cp.async ring (221 KB smem; prefetch distance 3 chunks)
//  - uniform one-commit-per-iteration wait_group discipline

#define THREADS 512

__device__ __half g_Wh[256 * 3072];            // W as fp16
__device__ __half g_feats[16384 * 3072];       // feats as fp16 (96 MB scratch)

static __device__ __forceinline__ uint32_t smem_u32(const void* p) {
    uint32_t a;
    asm("{ .reg .u64 t; cvta.to.shared.u64 t, %1; cvt.u32.u64 %0, t; }"
        : "=r"(a) : "l"(p));
    return a;
}
static __device__ __forceinline__ void ldsm4(uint32_t* r, uint32_t addr) {
    asm volatile("ldmatrix.sync.aligned.m8n8.x4.shared.b16 {%0,%1,%2,%3}, [%4];"
                 : "=r"(r[0]), "=r"(r[1]), "=r"(r[2]), "=r"(r[3]) : "r"(addr));
}
static __device__ __forceinline__ void mma_f16(float* d, const uint32_t* a,
                                               const uint32_t* b) {
    asm volatile("mma.sync.aligned.m16n8k16.row.col.f32.f16.f16.f32 "
                 "{%0,%1,%2,%3}, {%4,%5,%6,%7}, {%8,%9}, {%0,%1,%2,%3};"
                 : "+f"(d[0]), "+f"(d[1]), "+f"(d[2]), "+f"(d[3])
                 : "r"(a[0]), "r"(a[1]), "r"(a[2]), "r"(a[3]),
                   "r"(b[0]), "r"(b[1]));
}
static __device__ __forceinline__ void cpasync16(uint32_t dst, const void* src) {
    asm volatile("cp.async.ca.shared.global [%0], [%1], 16;"
                 :: "r"(dst), "l"(src) : "memory");
}
static __device__ __forceinline__ uint32_t h2bits(__half2 h) {
    return *reinterpret_cast<uint32_t*>(&h);
}
static __device__ __forceinline__ uint2 pack4(float x, float y, float z, float w) {
    return make_uint2(h2bits(__float22half2_rn(make_float2(x, y))),
                      h2bits(__float22half2_rn(make_float2(z, w))));
}

// SMEM per stage: A[128][72] + B[256][72] fp16, pitch 144 B (conflict-free)
#define LDA 72
#define PITCH (LDA * 2)
#define OFF_B (128 * PITCH)                   // 18432
#define STAGE_STRIDE (OFF_B + 256 * PITCH)    // 55296
#define NSTAGE 4
#define SMEM_BYTES (NSTAGE * STAGE_STRIDE)    // 221184 (< 227KB cap)

// ---- prologue: gather + feature build -> fp16 feats; also converts W ----
__global__ void __launch_bounds__(256)
feats_kernel(const int* __restrict__ pairs32, const float* __restrict__ hidden,
             const float* __restrict__ Wg) {
    __shared__ int sIs64;
    const int t    = threadIdx.x;
    const int lane = t & 31;
    const int wid  = t >> 5;

    if (blockIdx.x < 768) {   // fused W conversion
        const int i = blockIdx.x * 256 + t;
        float4 v = reinterpret_cast<const float4*>(Wg)[i];
        reinterpret_cast<uint2*>(g_Wh)[i] = pack4(v.x, v.y, v.z, v.w);
    }

    if (t == 0) {   // int64 pairs -> all odd 32-bit words zero (indices < 1024)
        int a = 0;
#pragma unroll
        for (int i = 1; i < 128; i += 2) a |= pairs32[i];
        sIs64 = (a == 0);
    }
    __syncthreads();

    const int row = blockIdx.x * 8 + wid;
    const int b   = row >> 9;
    int4 id;
    if (sIs64) {
        const long long* p64 = reinterpret_cast<const long long*>(pairs32) + (size_t)row * 4;
        id = make_int4((int)p64[0], (int)p64[1], (int)p64[2], (int)p64[3]);
    } else {
        id = reinterpret_cast<const int4*>(pairs32)[row];
    }

    const float* hb = hidden + (size_t)b * (size_t)(1024 * 1024);
    const float4* x0 = reinterpret_cast<const float4*>(hb + (size_t)id.x * 1024);
    const float4* x1 = reinterpret_cast<const float4*>(hb + (size_t)id.y * 1024);
    const float4* x2 = reinterpret_cast<const float4*>(hb + (size_t)id.z * 1024);
    const float4* x3 = reinterpret_cast<const float4*>(hb + (size_t)id.w * 1024);
    uint2* fr = reinterpret_cast<uint2*>(g_feats + (size_t)row * 3072);

#pragma unroll
    for (int j = 0; j < 8; ++j) {
        const int i = lane + j * 32;
        float4 a = x0[i], d = x1[i], e = x2[i], f = x3[i];
        float hx = 0.5f*(a.x+d.x), hy = 0.5f*(a.y+d.y),
              hz = 0.5f*(a.z+d.z), hw = 0.5f*(a.w+d.w);
        float tx = 0.5f*(e.x+f.x), ty = 0.5f*(e.y+f.y),
              tz = 0.5f*(e.z+f.z), tw = 0.5f*(e.w+f.w);
        fr[i]       = pack4(hx, hy, hz, hw);
        fr[i + 256] = pack4(tx, ty, tz, tw);
        fr[i + 512] = pack4(hx*tx, hy*ty, hz*tz, hw*tw);
    }
}

// ---- main GEMM: CTA 128(M) x 256(N), 16 warps (4x4), warp tile 32x64 ----
__global__ void __launch_bounds__(THREADS, 1)
gr_gemm_kernel(const float* __restrict__ bias, float* __restrict__ out)
{
    constexpr int KC  = 64;
    constexpr int NCH = 3072 / KC;   // 48

    extern __shared__ char dsm[];
    const uint32_t smb = smem_u32(dsm);
    __shared__ float sBias[256];

    const int t    = threadIdx.x;
    const int lane = t & 31;
    const int w    = t >> 5;
    const int wm   = w >> 2;       // 0..3 : 32-row m group
    const int wn   = w & 3;        // 0..3 : 64-col n group
    const int row0 = blockIdx.x * 128;

    if (t < 256) sBias[t] = bias[t];

    // staging (512 thr): A 4 thr/row x 16 cols (32 B), B 2 thr/row x 32 cols (64 B)
    const int arow = t >> 2;
    const int ak   = (t & 3) << 4;
    const __half* asrc = g_feats + (size_t)(row0 + arow) * 3072 + ak;
    const uint32_t adst = arow * PITCH + ak * 2;
    const int brow = t >> 1;
    const int bk   = (t & 1) << 5;
    const __half* bsrc = g_Wh + (size_t)brow * 3072 + bk;
    const uint32_t bdst = OFF_B + brow * PITCH + bk * 2;

    auto prefetch = [&](int c) {
        const uint32_t buf = smb + (c % NSTAGE) * STAGE_STRIDE;
        const __half* as = asrc + c * KC;
        const __half* bs = bsrc + c * KC;
#pragma unroll
        for (int i = 0; i < 2; ++i) cpasync16(buf + adst + i * 16, as + i * 8);
#pragma unroll
        for (int i = 0; i < 4; ++i) cpasync16(buf + bdst + i * 16, bs + i * 8);
    };

    float acc[2][8][4];
#pragma unroll
    for (int i = 0; i < 2; ++i)
#pragma unroll
        for (int j = 0; j < 8; ++j)
#pragma unroll
            for (int q = 0; q < 4; ++q) acc[i][j][q] = 0.f;

    const int lr = lane & 15;
    const int lh = (lane >> 4) << 3;
    const uint32_t aOff = (wm * 32 + lr) * PITCH + lh * 2;
    const uint32_t bOff = OFF_B + (wn * 64 + lr) * PITCH + lh * 2;

    // prologue: stage chunks 0..2 (3 committed groups outstanding)
    prefetch(0); asm volatile("cp.async.commit_group;");
    prefetch(1); asm volatile("cp.async.commit_group;");
    prefetch(2); asm volatile("cp.async.commit_group;");

    for (int c = 0; c < NCH; ++c) {
        // 3 groups pending -> wait_group 2 drains exactly chunk c's group
        asm volatile("cp.async.wait_group 2;" ::: "memory");
        __syncthreads();                      // slot (c-1)%4 free for reuse
        if (c + 3 < NCH) prefetch(c + 3);     // writes slot (c-1)%4
        asm volatile("cp.async.commit_group;");   // always one commit/iter

        const uint32_t base  = smb + (c % NSTAGE) * STAGE_STRIDE;
        const uint32_t aBase = base + aOff;
        const uint32_t bBase = base + bOff;

        // A-frag double buffer: A(kk+1) loaded before MMAs of kk
        uint32_t af[2][2][4];
#pragma unroll
        for (int mt = 0; mt < 2; ++mt)
            ldsm4(af[0][mt], aBase + mt * 16 * PITCH);

#pragma unroll
        for (int kk = 0; kk < 4; ++kk) {
            const int cur = kk & 1;
            const uint32_t kb = kk * 32;
            uint32_t bf[8][2];
#pragma unroll
            for (int p = 0; p < 4; ++p) {
                uint32_t r[4];
                ldsm4(r, bBase + p * 16 * PITCH + kb);
                bf[2*p][0]   = r[0]; bf[2*p][1]   = r[2];
                bf[2*p+1][0] = r[1]; bf[2*p+1][1] = r[3];
            }
            if (kk < 3) {
#pragma unroll
                for (int mt = 0; mt < 2; ++mt)
                    ldsm4(af[cur ^ 1][mt], aBase + mt * 16 * PITCH + kb + 32);
            }
#pragma unroll
            for (int mt = 0; mt < 2; ++mt)
#pragma unroll
                for (int n8 = 0; n8 < 8; ++n8)
                    mma_f16(acc[mt][n8], af[cur][mt], bf[n8]);
        }
    }

    // ---- epilogue: bias + fp32 store ----
    const int g  = lane >> 2;
    const int tq = lane & 3;
#pragma unroll
    for (int mt = 0; mt < 2; ++mt) {
        const int r0g = row0 + wm * 32 + mt * 16 + g;
#pragma unroll
        for (int n8 = 0; n8 < 8; ++n8) {
            const int col = wn * 64 + n8 * 8 + tq * 2;
            const float bx = sBias[col], by = sBias[col + 1];
            float* o0 = out + (size_t)r0g * 256 + col;
            float* o1 = o0 + 8 * 256;
            *reinterpret_cast<float2*>(o0) =
                make_float2(acc[mt][n8][0] + bx, acc[mt][n8][1] + by);
            *reinterpret_cast<float2*>(o1) =
                make_float2(acc[mt][n8][2] + bx, acc[mt][n8][3] + by);
        }
    }
}

extern "C" void kernel_launch(void* const* d_in, const int* in_sizes, int n_in,
                              void* d_out, int out_size) {
    (void)in_sizes; (void)n_in; (void)out_size;
    const int*   pairs  = (const int*)  d_in[0];
    const float* hidden = (const float*)d_in[1];
    const float* W      = (const float*)d_in[2];
    const float* bias   = (const float*)d_in[3];
    float*       out    = (float*)d_out;

    static bool attr_set = false;
    if (!attr_set) {
        cudaFuncSetAttribute(gr_gemm_kernel,
                             cudaFuncAttributeMaxDynamicSharedMemorySize, SMEM_BYTES);
        attr_set = true;
    }
    feats_kernel<<<16384 / 8, 256>>>(pairs, hidden, W);
    gr_gemm_kernel<<<16384 / 128, THREADS, SMEM_BYTES>>>(bias, out);
}

// round 14
// speedup vs baseline: 1.1349x; 1.1349x over previous
#include <cuda_runtime.h>
#include <cuda_fp16.h>
#include <cstdint>

// B=32, P=512, S=1024, H=1024, R=256, K3=3072
// out[M=16384,256] = feats[M,3072] @ W^T + bias
// R14: exact R12 GEMM (512 thr, 16 warps 4x4, warp tile 32x64, KC=64,
// NSTAGE=3 ring, one barrier/chunk) with ONE change: cp.async.cg instead of
// .ca (A/B tiles are single-use -> L1 allocation is pure pollution).
// R13's NSTAGE=4 + k-loop restructure reverted (regressed 90.5->134.6 us:
// 7KB L1 carveout thrashed by .ca fills + worse ldsm/MMA schedule).

#define THREADS 512

__device__ __half g_Wh[256 * 3072];            // W as fp16
__device__ __half g_feats[16384 * 3072];       // feats as fp16 (96 MB scratch)

static __device__ __forceinline__ uint32_t smem_u32(const void* p) {
    uint32_t a;
    asm("{ .reg .u64 t; cvta.to.shared.u64 t, %1; cvt.u32.u64 %0, t; }"
        : "=r"(a) : "l"(p));
    return a;
}
static __device__ __forceinline__ void ldsm4(uint32_t* r, uint32_t addr) {
    asm volatile("ldmatrix.sync.aligned.m8n8.x4.shared.b16 {%0,%1,%2,%3}, [%4];"
                 : "=r"(r[0]), "=r"(r[1]), "=r"(r[2]), "=r"(r[3]) : "r"(addr));
}
static __device__ __forceinline__ void mma_f16(float* d, const uint32_t* a,
                                               const uint32_t* b) {
    asm volatile("mma.sync.aligned.m16n8k16.row.col.f32.f16.f16.f32 "
                 "{%0,%1,%2,%3}, {%4,%5,%6,%7}, {%8,%9}, {%0,%1,%2,%3};"
                 : "+f"(d[0]), "+f"(d[1]), "+f"(d[2]), "+f"(d[3])
                 : "r"(a[0]), "r"(a[1]), "r"(a[2]), "r"(a[3]),
                   "r"(b[0]), "r"(b[1]));
}
static __device__ __forceinline__ void cpasync16(uint32_t dst, const void* src) {
    asm volatile("cp.async.cg.shared.global [%0], [%1], 16;"
                 :: "r"(dst), "l"(src) : "memory");
}
static __device__ __forceinline__ uint32_t h2bits(__half2 h) {
    return *reinterpret_cast<uint32_t*>(&h);
}
static __device__ __forceinline__ uint2 pack4(float x, float y, float z, float w) {
    return make_uint2(h2bits(__float22half2_rn(make_float2(x, y))),
                      h2bits(__float22half2_rn(make_float2(z, w))));
}

// SMEM per stage: A[128][72] + B[256][72] fp16, pitch 144 B (conflict-free)
#define LDA 72
#define PITCH (LDA * 2)
#define OFF_B (128 * PITCH)                   // 18432
#define STAGE_STRIDE (OFF_B + 256 * PITCH)    // 55296
#define NSTAGE 3
#define SMEM_BYTES (NSTAGE * STAGE_STRIDE)    // 165888

// ---- prologue: gather + feature build -> fp16 feats; also converts W ----
__global__ void __launch_bounds__(256)
feats_kernel(const int* __restrict__ pairs32, const float* __restrict__ hidden,
             const float* __restrict__ Wg) {
    __shared__ int sIs64;
    const int t    = threadIdx.x;
    const int lane = t & 31;
    const int wid  = t >> 5;

    if (blockIdx.x < 768) {   // fused W conversion
        const int i = blockIdx.x * 256 + t;
        float4 v = reinterpret_cast<const float4*>(Wg)[i];
        reinterpret_cast<uint2*>(g_Wh)[i] = pack4(v.x, v.y, v.z, v.w);
    }

    if (t == 0) {   // int64 pairs -> all odd 32-bit words zero (indices < 1024)
        int a = 0;
#pragma unroll
        for (int i = 1; i < 128; i += 2) a |= pairs32[i];
        sIs64 = (a == 0);
    }
    __syncthreads();

    const int row = blockIdx.x * 8 + wid;
    const int b   = row >> 9;
    int4 id;
    if (sIs64) {
        const long long* p64 = reinterpret_cast<const long long*>(pairs32) + (size_t)row * 4;
        id = make_int4((int)p64[0], (int)p64[1], (int)p64[2], (int)p64[3]);
    } else {
        id = reinterpret_cast<const int4*>(pairs32)[row];
    }

    const float* hb = hidden + (size_t)b * (size_t)(1024 * 1024);
    const float4* x0 = reinterpret_cast<const float4*>(hb + (size_t)id.x * 1024);
    const float4* x1 = reinterpret_cast<const float4*>(hb + (size_t)id.y * 1024);
    const float4* x2 = reinterpret_cast<const float4*>(hb + (size_t)id.z * 1024);
    const float4* x3 = reinterpret_cast<const float4*>(hb + (size_t)id.w * 1024);
    uint2* fr = reinterpret_cast<uint2*>(g_feats + (size_t)row * 3072);

#pragma unroll
    for (int j = 0; j < 8; ++j) {
        const int i = lane + j * 32;
        float4 a = x0[i], d = x1[i], e = x2[i], f = x3[i];
        float hx = 0.5f*(a.x+d.x), hy = 0.5f*(a.y+d.y),
              hz = 0.5f*(a.z+d.z), hw = 0.5f*(a.w+d.w);
        float tx = 0.5f*(e.x+f.x), ty = 0.5f*(e.y+f.y),
              tz = 0.5f*(e.z+f.z), tw = 0.5f*(e.w+f.w);
        fr[i]       = pack4(hx, hy, hz, hw);
        fr[i + 256] = pack4(tx, ty, tz, tw);
        fr[i + 512] = pack4(hx*tx, hy*ty, hz*tz, hw*tw);
    }
}

// ---- main GEMM: CTA 128(M) x 256(N), 16 warps (4x4), warp tile 32x64 ----
__global__ void __launch_bounds__(THREADS, 1)
gr_gemm_kernel(const float* __restrict__ bias, float* __restrict__ out)
{
    constexpr int KC  = 64;
    constexpr int NCH = 3072 / KC;   // 48

    extern __shared__ char dsm[];
    const uint32_t smb = smem_u32(dsm);
    __shared__ float sBias[256];

    const int t    = threadIdx.x;
    const int lane = t & 31;
    const int w    = t >> 5;
    const int wm   = w >> 2;       // 0..3 : 32-row m group
    const int wn   = w & 3;        // 0..3 : 64-col n group
    const int row0 = blockIdx.x * 128;

    if (t < 256) sBias[t] = bias[t];

    // staging (512 thr): A 4 thr/row x 16 cols (32 B), B 2 thr/row x 32 cols (64 B)
    const int arow = t >> 2;
    const int ak   = (t & 3) << 4;
    const __half* asrc = g_feats + (size_t)(row0 + arow) * 3072 + ak;
    const uint32_t adst = arow * PITCH + ak * 2;
    const int brow = t >> 1;
    const int bk   = (t & 1) << 5;
    const __half* bsrc = g_Wh + (size_t)brow * 3072 + bk;
    const uint32_t bdst = OFF_B + brow * PITCH + bk * 2;

    auto prefetch = [&](int c) {
        const uint32_t buf = smb + (c % NSTAGE) * STAGE_STRIDE;
        const __half* as = asrc + c * KC;
        const __half* bs = bsrc + c * KC;
#pragma unroll
        for (int i = 0; i < 2; ++i) cpasync16(buf + adst + i * 16, as + i * 8);
#pragma unroll
        for (int i = 0; i < 4; ++i) cpasync16(buf + bdst + i * 16, bs + i * 8);
        asm volatile("cp.async.commit_group;");
    };

    float acc[2][8][4];
#pragma unroll
    for (int i = 0; i < 2; ++i)
#pragma unroll
        for (int j = 0; j < 8; ++j)
#pragma unroll
            for (int q = 0; q < 4; ++q) acc[i][j][q] = 0.f;

    const int lr = lane & 15;
    const int lh = (lane >> 4) << 3;
    const uint32_t aOff = (wm * 32 + lr) * PITCH + lh * 2;
    const uint32_t bOff = OFF_B + (wn * 64 + lr) * PITCH + lh * 2;

    prefetch(0);
    prefetch(1);

    for (int c = 0; c < NCH; ++c) {
        asm volatile("cp.async.wait_group 1;" ::: "memory");   // chunk c ready
        __syncthreads();                     // + slot (c-1)%3 free
        if (c + 2 < NCH) prefetch(c + 2);    // writes slot (c-1)%3

        const uint32_t base  = smb + (c % NSTAGE) * STAGE_STRIDE;
        const uint32_t aBase = base + aOff;
        const uint32_t bBase = base + bOff;

#pragma unroll
        for (int kk = 0; kk < 4; ++kk) {
            const uint32_t kb = kk * 32;
            uint32_t af[2][4], bf[8][2];
#pragma unroll
            for (int mt = 0; mt < 2; ++mt)
                ldsm4(af[mt], aBase + mt * 16 * PITCH + kb);
#pragma unroll
            for (int p = 0; p < 4; ++p) {
                uint32_t r[4];
                ldsm4(r, bBase + p * 16 * PITCH + kb);
                bf[2*p][0]   = r[0]; bf[2*p][1]   = r[2];
                bf[2*p+1][0] = r[1]; bf[2*p+1][1] = r[3];
            }
#pragma unroll
            for (int mt = 0; mt < 2; ++mt)
#pragma unroll
                for (int n8 = 0; n8 < 8; ++n8)
                    mma_f16(acc[mt][n8], af[mt], bf[n8]);
        }
    }

    // ---- epilogue: bias + fp32 store ----
    const int g  = lane >> 2;
    const int tq = lane & 3;
#pragma unroll
    for (int mt = 0; mt < 2; ++mt) {
        const int r0g = row0 + wm * 32 + mt * 16 + g;
#pragma unroll
        for (int n8 = 0; n8 < 8; ++n8) {
            const int col = wn * 64 + n8 * 8 + tq * 2;
            const float bx = sBias[col], by = sBias[col + 1];
            float* o0 = out + (size_t)r0g * 256 + col;
            float* o1 = o0 + 8 * 256;
            *reinterpret_cast<float2*>(o0) =
                make_float2(acc[mt][n8][0] + bx, acc[mt][n8][1] + by);
            *reinterpret_cast<float2*>(o1) =
                make_float2(acc[mt][n8][2] + bx, acc[mt][n8][3] + by);
        }
    }
}

extern "C" void kernel_launch(void* const* d_in, const int* in_sizes, int n_in,
                              void* d_out, int out_size) {
    (void)in_sizes; (void)n_in; (void)out_size;
    const int*   pairs  = (const int*)  d_in[0];
    const float* hidden = (const float*)d_in[1];
    const float* W      = (const float*)d_in[2];
    const float* bias   = (const float*)d_in[3];
    float*       out    = (float*)d_out;

    static bool attr_set = false;
    if (!attr_set) {
        cudaFuncSetAttribute(gr_gemm_kernel,
                             cudaFuncAttributeMaxDynamicSharedMemorySize, SMEM_BYTES);
        attr_set = true;
    }
    feats_kernel<<<16384 / 8, 256>>>(pairs, hidden, W);
    gr_gemm_kernel<<<16384 / 128, THREADS, SMEM_BYTES>>>(bias, out);
}

// round 15
// speedup vs baseline: 1.3170x; 1.1605x over previous
#include <cuda_runtime.h>
#include <cuda_fp16.h>
#include <cstdint>

// B=32, P=512, S=1024, H=1024, R=256, K3=3072
// out[M=16384,256] = feats[M,3072] @ W^T + bias
// R15: exact R12 GEMM config (512 thr, 16 warps 4x4, warp tile 32x64, KC=64,
// NSTAGE=3, cp.async.CA — .cg falsified in R14) + ONE isolated change:
// A-fragment double-buffering across k-steps (hide ldsm->HMMA RAW latency).

#define THREADS 512

__device__ __half g_Wh[256 * 3072];            // W as fp16
__device__ __half g_feats[16384 * 3072];       // feats as fp16 (96 MB scratch)

static __device__ __forceinline__ uint32_t smem_u32(const void* p) {
    uint32_t a;
    asm("{ .reg .u64 t; cvta.to.shared.u64 t, %1; cvt.u32.u64 %0, t; }"
        : "=r"(a) : "l"(p));
    return a;
}
static __device__ __forceinline__ void ldsm4(uint32_t* r, uint32_t addr) {
    asm volatile("ldmatrix.sync.aligned.m8n8.x4.shared.b16 {%0,%1,%2,%3}, [%4];"
                 : "=r"(r[0]), "=r"(r[1]), "=r"(r[2]), "=r"(r[3]) : "r"(addr));
}
static __device__ __forceinline__ void mma_f16(float* d, const uint32_t* a,
                                               const uint32_t* b) {
    asm volatile("mma.sync.aligned.m16n8k16.row.col.f32.f16.f16.f32 "
                 "{%0,%1,%2,%3}, {%4,%5,%6,%7}, {%8,%9}, {%0,%1,%2,%3};"
                 : "+f"(d[0]), "+f"(d[1]), "+f"(d[2]), "+f"(d[3])
                 : "r"(a[0]), "r"(a[1]), "r"(a[2]), "r"(a[3]),
                   "r"(b[0]), "r"(b[1]));
}
static __device__ __forceinline__ void cpasync16(uint32_t dst, const void* src) {
    asm volatile("cp.async.ca.shared.global [%0], [%1], 16;"
                 :: "r"(dst), "l"(src) : "memory");
}
static __device__ __forceinline__ uint32_t h2bits(__half2 h) {
    return *reinterpret_cast<uint32_t*>(&h);
}
static __device__ __forceinline__ uint2 pack4(float x, float y, float z, float w) {
    return make_uint2(h2bits(__float22half2_rn(make_float2(x, y))),
                      h2bits(__float22half2_rn(make_float2(z, w))));
}

// SMEM per stage: A[128][72] + B[256][72] fp16, pitch 144 B (conflict-free)
#define LDA 72
#define PITCH (LDA * 2)
#define OFF_B (128 * PITCH)                   // 18432
#define STAGE_STRIDE (OFF_B + 256 * PITCH)    // 55296
#define NSTAGE 3
#define SMEM_BYTES (NSTAGE * STAGE_STRIDE)    // 165888

// ---- prologue: gather + feature build -> fp16 feats; also converts W ----
__global__ void __launch_bounds__(256)
feats_kernel(const int* __restrict__ pairs32, const float* __restrict__ hidden,
             const float* __restrict__ Wg) {
    __shared__ int sIs64;
    const int t    = threadIdx.x;
    const int lane = t & 31;
    const int wid  = t >> 5;

    if (blockIdx.x < 768) {   // fused W conversion
        const int i = blockIdx.x * 256 + t;
        float4 v = reinterpret_cast<const float4*>(Wg)[i];
        reinterpret_cast<uint2*>(g_Wh)[i] = pack4(v.x, v.y, v.z, v.w);
    }

    if (t == 0) {   // int64 pairs -> all odd 32-bit words zero (indices < 1024)
        int a = 0;
#pragma unroll
        for (int i = 1; i < 128; i += 2) a |= pairs32[i];
        sIs64 = (a == 0);
    }
    __syncthreads();

    const int row = blockIdx.x * 8 + wid;
    const int b   = row >> 9;
    int4 id;
    if (sIs64) {
        const long long* p64 = reinterpret_cast<const long long*>(pairs32) + (size_t)row * 4;
        id = make_int4((int)p64[0], (int)p64[1], (int)p64[2], (int)p64[3]);
    } else {
        id = reinterpret_cast<const int4*>(pairs32)[row];
    }

    const float* hb = hidden + (size_t)b * (size_t)(1024 * 1024);
    const float4* x0 = reinterpret_cast<const float4*>(hb + (size_t)id.x * 1024);
    const float4* x1 = reinterpret_cast<const float4*>(hb + (size_t)id.y * 1024);
    const float4* x2 = reinterpret_cast<const float4*>(hb + (size_t)id.z * 1024);
    const float4* x3 = reinterpret_cast<const float4*>(hb + (size_t)id.w * 1024);
    uint2* fr = reinterpret_cast<uint2*>(g_feats + (size_t)row * 3072);

#pragma unroll
    for (int j = 0; j < 8; ++j) {
        const int i = lane + j * 32;
        float4 a = x0[i], d = x1[i], e = x2[i], f = x3[i];
        float hx = 0.5f*(a.x+d.x), hy = 0.5f*(a.y+d.y),
              hz = 0.5f*(a.z+d.z), hw = 0.5f*(a.w+d.w);
        float tx = 0.5f*(e.x+f.x), ty = 0.5f*(e.y+f.y),
              tz = 0.5f*(e.z+f.z), tw = 0.5f*(e.w+f.w);
        fr[i]       = pack4(hx, hy, hz, hw);
        fr[i + 256] = pack4(tx, ty, tz, tw);
        fr[i + 512] = pack4(hx*tx, hy*ty, hz*tz, hw*tw);
    }
}

// ---- main GEMM: CTA 128(M) x 256(N), 16 warps (4x4), warp tile 32x64 ----
__global__ void __launch_bounds__(THREADS, 1)
gr_gemm_kernel(const float* __restrict__ bias, float* __restrict__ out)
{
    constexpr int KC  = 64;
    constexpr int NCH = 3072 / KC;   // 48

    extern __shared__ char dsm[];
    const uint32_t smb = smem_u32(dsm);
    __shared__ float sBias[256];

    const int t    = threadIdx.x;
    const int lane = t & 31;
    const int w    = t >> 5;
    const int wm   = w >> 2;       // 0..3 : 32-row m group
    const int wn   = w & 3;        // 0..3 : 64-col n group
    const int row0 = blockIdx.x * 128;

    if (t < 256) sBias[t] = bias[t];

    // staging (512 thr): A 4 thr/row x 16 cols (32 B), B 2 thr/row x 32 cols (64 B)
    const int arow = t >> 2;
    const int ak   = (t & 3) << 4;
    const __half* asrc = g_feats + (size_t)(row0 + arow) * 3072 + ak;
    const uint32_t adst = arow * PITCH + ak * 2;
    const int brow = t >> 1;
    const int bk   = (t & 1) << 5;
    const __half* bsrc = g_Wh + (size_t)brow * 3072 + bk;
    const uint32_t bdst = OFF_B + brow * PITCH + bk * 2;

    auto prefetch = [&](int c) {
        const uint32_t buf = smb + (c % NSTAGE) * STAGE_STRIDE;
        const __half* as = asrc + c * KC;
        const __half* bs = bsrc + c * KC;
#pragma unroll
        for (int i = 0; i < 2; ++i) cpasync16(buf + adst + i * 16, as + i * 8);
#pragma unroll
        for (int i = 0; i < 4; ++i) cpasync16(buf + bdst + i * 16, bs + i * 8);
        asm volatile("cp.async.commit_group;");
    };

    float acc[2][8][4];
#pragma unroll
    for (int i = 0; i < 2; ++i)
#pragma unroll
        for (int j = 0; j < 8; ++j)
#pragma unroll
            for (int q = 0; q < 4; ++q) acc[i][j][q] = 0.f;

    const int lr = lane & 15;
    const int lh = (lane >> 4) << 3;
    const uint32_t aOff = (wm * 32 + lr) * PITCH + lh * 2;
    const uint32_t bOff = OFF_B + (wn * 64 + lr) * PITCH + lh * 2;

    prefetch(0);
    prefetch(1);

    for (int c = 0; c < NCH; ++c) {
        asm volatile("cp.async.wait_group 1;" ::: "memory");   // chunk c ready
        __syncthreads();                     // + slot (c-1)%3 free
        if (c + 2 < NCH) prefetch(c + 2);    // writes slot (c-1)%3

        const uint32_t base  = smb + (c % NSTAGE) * STAGE_STRIDE;
        const uint32_t aBase = base + aOff;
        const uint32_t bBase = base + bOff;

        // A-frag double buffer: A(kk+1) in flight while MMAs of kk execute
        uint32_t af[2][2][4];
#pragma unroll
        for (int mt = 0; mt < 2; ++mt)
            ldsm4(af[0][mt], aBase + mt * 16 * PITCH);

#pragma unroll
        for (int kk = 0; kk < 4; ++kk) {
            const int cur = kk & 1;
            const uint32_t kb = kk * 32;
            uint32_t bf[8][2];
#pragma unroll
            for (int p = 0; p < 4; ++p) {
                uint32_t r[4];
                ldsm4(r, bBase + p * 16 * PITCH + kb);
                bf[2*p][0]   = r[0]; bf[2*p][1]   = r[2];
                bf[2*p+1][0] = r[1]; bf[2*p+1][1] = r[3];
            }
            if (kk < 3) {
#pragma unroll
                for (int mt = 0; mt < 2; ++mt)
                    ldsm4(af[cur ^ 1][mt], aBase + mt * 16 * PITCH + kb + 32);
            }
#pragma unroll
            for (int mt = 0; mt < 2; ++mt)
#pragma unroll
                for (int n8 = 0; n8 < 8; ++n8)
                    mma_f16(acc[mt][n8], af[cur][mt], bf[n8]);
        }
    }

    // ---- epilogue: bias + fp32 store ----
    const int g  = lane >> 2;
    const int tq = lane & 3;
#pragma unroll
    for (int mt = 0; mt < 2; ++mt) {
        const int r0g = row0 + wm * 32 + mt * 16 + g;
#pragma unroll
        for (int n8 = 0; n8 < 8; ++n8) {
            const int col = wn * 64 + n8 * 8 + tq * 2;
            const float bx = sBias[col], by = sBias[col + 1];
            float* o0 = out + (size_t)r0g * 256 + col;
            float* o1 = o0 + 8 * 256;
            *reinterpret_cast<float2*>(o0) =
                make_float2(acc[mt][n8][0] + bx, acc[mt][n8][1] + by);
            *reinterpret_cast<float2*>(o1) =
                make_float2(acc[mt][n8][2] + bx, acc[mt][n8][3] + by);
        }
    }
}

extern "C" void kernel_launch(void* const* d_in, const int* in_sizes, int n_in,
                              void* d_out, int out_size) {
    (void)in_sizes; (void)n_in; (void)out_size;
    const int*   pairs  = (const int*)  d_in[0];
    const float* hidden = (const float*)d_in[1];
    const float* W      = (const float*)d_in[2];
    const float* bias   = (const float*)d_in[3];
    float*       out    = (float*)d_out;

    static bool attr_set = false;
    if (!attr_set) {
        cudaFuncSetAttribute(gr_gemm_kernel,
                             cudaFuncAttributeMaxDynamicSharedMemorySize, SMEM_BYTES);
        attr_set = true;
    }
    feats_kernel<<<16384 / 8, 256>>>(pairs, hidden, W);
    gr_gemm_kernel<<<16384 / 128, THREADS, SMEM_BYTES>>>(bias, out);
}